// round 12
// baseline (speedup 1.0000x reference)
#include <cuda_runtime.h>
#include <cuda_bf16.h>
#include <cstdint>

#define PW 50
#define NPIX 2500            // 50*50 padded pixel rows per (b,u,v)
#define PLANE 2304           // 48*48
#define CH_STR 112896        // 7*7*2304
#define RPB 512              // pixel rows per block (8 warps x 64)
#define MARG 64              // sA margin (covers tap shifts +-51)
#define SA_ROWS 640
#define LO_OFF 10240         // lo plane offset within one buffer
#define SA_BYTES 20480       // one buffer: hi + lo planes
#define SBF_BYTES 20736      // 81*32*8
#define SMEM_BYTES (SBF_BYTES + 2 * SA_BYTES)   // 61696
#define NTHREADS 256

__device__ __forceinline__ uint32_t cvt2(float lo, float hi) {   // {lo16,hi16} bf16x2
    uint32_t r;
    asm("cvt.rn.bf16x2.f32 %0, %1, %2;" : "=r"(r) : "f"(hi), "f"(lo));
    return r;
}
__device__ __forceinline__ void ldm4(uint32_t& r0, uint32_t& r1, uint32_t& r2,
                                     uint32_t& r3, uint32_t a) {
    asm volatile("ldmatrix.sync.aligned.m8n8.x4.shared.b16 {%0,%1,%2,%3}, [%4];"
                 : "=r"(r0), "=r"(r1), "=r"(r2), "=r"(r3) : "r"(a));
}
__device__ __forceinline__ void mma16816(float* c, uint32_t a0, uint32_t a1,
                                         uint32_t a2, uint32_t a3,
                                         uint32_t b0, uint32_t b1) {
    asm volatile(
        "mma.sync.aligned.m16n8k16.row.col.f32.bf16.bf16.f32 "
        "{%0,%1,%2,%3}, {%4,%5,%6,%7}, {%8,%9}, {%0,%1,%2,%3};"
        : "+f"(c[0]), "+f"(c[1]), "+f"(c[2]), "+f"(c[3])
        : "r"(a0), "r"(a1), "r"(a2), "r"(a3), "r"(b0), "r"(b1));
}
__device__ __forceinline__ void sts128(uint32_t a, uint32_t r0, uint32_t r1,
                                       uint32_t r2, uint32_t r3) {
    asm volatile("st.shared.v4.b32 [%0], {%1,%2,%3,%4};"
                 :: "r"(a), "r"(r0), "r"(r1), "r"(r2), "r"(r3) : "memory");
}

// x: [2][8][7][7][48][48] f32, conv: [8][648], bias: [8], out: [2][8][7][7][48][48] f32
__global__ __launch_bounds__(NTHREADS) void conv4d_mma(
    const float* __restrict__ x,
    const float* __restrict__ conv,
    const float* __restrict__ bias,
    float* __restrict__ out)
{
    extern __shared__ char smem[];
    uint2* sBF = (uint2*)smem;                 // B fragments: [tap][lane] {hi,lo}
    uint32_t sbase;
    asm("{ .reg .u64 t; cvta.to.shared.u64 t, %1; cvt.u32.u64 %0, t; }"
        : "=r"(sbase) : "l"(smem));
    const uint32_t sA0 = sbase + SBF_BYTES;    // buffer 0 (hi at +0, lo at +LO_OFF)

    const int tid  = threadIdx.x;
    const int wid  = tid >> 5;
    const int lane = tid & 31;
    const int R0   = blockIdx.x * RPB;
    const int uv   = blockIdx.y;
    const int u    = uv / 7, v = uv % 7;
    const int b    = blockIdx.z;

    // ---- precompute B fragments ----
    for (int e = tid; e < 81 * 32; e += NTHREADS) {
        const int tap = e >> 5, ln = e & 31;
        const int o = ln >> 2, c0 = (ln & 3) * 2;
        const float w0 = conv[o * 648 + tap * 8 + c0];
        const float w1 = conv[o * 648 + tap * 8 + c0 + 1];
        const uint32_t hi01 = cvt2(w0, w1);
        const float hf0 = __uint_as_float(hi01 << 16);
        const float hf1 = __uint_as_float(hi01 & 0xFFFF0000u);
        sBF[e] = make_uint2(hi01, cvt2(w0 - hf0, w1 - hf1));
    }
    // ---- zero both sA buffers (margins/padding stay 0) ----
    {
        const uint4 z = make_uint4(0, 0, 0, 0);
        uint4* p4 = (uint4*)(smem + SBF_BYTES);
        for (int j = tid; j < 2 * SA_BYTES / 16; j += NTHREADS) p4[j] = z;
    }

    // ---- valid (i0,i1) phases ----
    int ph_poff[9], ph_tap[9], nph = 0;
    #pragma unroll
    for (int i0 = 0; i0 < 3; i0++) {
        const int uu = u + i0 - 1;
        if (uu < 0 || uu >= 7) continue;
        #pragma unroll
        for (int i1 = 0; i1 < 3; i1++) {
            const int vv = v + i1 - 1;
            if (vv < 0 || vv >= 7) continue;
            ph_poff[nph] = (uu * 7 + vv) * PLANE;
            ph_tap[nph]  = (i0 * 3 + i1) * 9;
            nph++;
        }
    }
    const float* xb = x + (size_t)b * 8 * CH_STR;

    // ---- per-thread transpose rows (phase-independent) ----
    int rw_src[3]; uint32_t rw_sa[3]; bool rw_ok[3];
    #pragma unroll
    for (int k = 0; k < 3; k++) {
        const int j = tid + k * NTHREADS;
        const int m = R0 - MARG + j;
        const int mc = m < 0 ? 0 : m;
        const int hp = mc / PW, wp = mc - hp * PW;
        rw_ok[k]  = (j < SA_ROWS) && (m >= 0) && (m < NPIX) &&
                    (hp >= 1) && (hp <= 48) && (wp >= 1) && (wp <= 48);
        rw_src[k] = (hp - 1) * 48 + (wp - 1);
        rw_sa[k]  = sA0 + j * 16;
    }

    // ---- per-warp ldmatrix base addresses ----
    const int lnrow = lane & 15;
    const uint32_t plane_off = (lane < 16) ? 0u : (uint32_t)LO_OFF;
    uint32_t abase[4];
    #pragma unroll
    for (int t = 0; t < 4; t++)
        abase[t] = sA0 + plane_off + (MARG + wid * 64 + t * 16 + lnrow) * 16;

    float acc[4][4];
    #pragma unroll
    for (int t = 0; t < 4; t++)
        #pragma unroll
        for (int i = 0; i < 4; i++) acc[t][i] = 0.0f;

    // helper lambda: cvt + store one row's 8 values to buffer `boff`
    auto store_row = [&](int k, const float* vch, uint32_t boff) {
        uint32_t hi[4], lo[4];
        #pragma unroll
        for (int q = 0; q < 4; q++) {
            hi[q] = cvt2(vch[2 * q], vch[2 * q + 1]);
            const float hf0 = __uint_as_float(hi[q] << 16);
            const float hf1 = __uint_as_float(hi[q] & 0xFFFF0000u);
            lo[q] = cvt2(vch[2 * q] - hf0, vch[2 * q + 1] - hf1);
        }
        sts128(rw_sa[k] + boff, hi[0], hi[1], hi[2], hi[3]);
        sts128(rw_sa[k] + boff + LO_OFF, lo[0], lo[1], lo[2], lo[3]);
    };

    // ---- prologue: transpose phase 0 into buffer 0 ----
    {
        const float* src0 = xb + ph_poff[0];
        #pragma unroll
        for (int k = 0; k < 3; k++) {
            if (!rw_ok[k]) continue;
            float vch[8];
            #pragma unroll
            for (int c = 0; c < 8; c++) vch[c] = __ldg(src0 + rw_src[k] + c * CH_STR);
            store_row(k, vch, 0u);
        }
    }
    __syncthreads();

    for (int p = 0; p < nph; p++) {
        const uint32_t abuf = (uint32_t)(p & 1) * SA_BYTES;
        const uint32_t bbuf = (uint32_t)((p + 1) & 1) * SA_BYTES;
        const bool pre = (p + 1 < nph);

        // prefetch next phase's x into registers (latency hidden behind MMAs)
        float nx[3][8];
        if (pre) {
            const float* src0 = xb + ph_poff[p + 1];
            #pragma unroll
            for (int k = 0; k < 3; k++) {
                if (!rw_ok[k]) continue;
                #pragma unroll
                for (int c = 0; c < 8; c++)
                    nx[k][c] = __ldg(src0 + rw_src[k] + c * CH_STR);
            }
        }

        // MMAs of phase p
        const int tapbase = ph_tap[p];
        #pragma unroll
        for (int t9 = 0; t9 < 9; t9++) {
            const int s16 = ((t9 / 3 - 1) * PW + (t9 % 3 - 1)) * 16;
            const uint2 bf = sBF[(tapbase + t9) * 32 + lane];
            #pragma unroll
            for (int t = 0; t < 4; t++) {
                uint32_t r0, r1, r2, r3;
                ldm4(r0, r1, r2, r3, abase[t] + abuf + s16);
                mma16816(acc[t], r0, r1, r2, r3, bf.x, bf.x);   // (xhi+xlo)*Whi
                mma16816(acc[t], r0, r1, r2, r3, bf.y, 0u);     // xhi*Wlo
            }
        }

        // store next phase into the other buffer
        if (pre) {
            #pragma unroll
            for (int k = 0; k < 3; k++)
                if (rw_ok[k]) store_row(k, nx[k], bbuf);
        }
        __syncthreads();
    }

    // ---- epilogue ----
    const int oc0 = (lane & 3) * 2;
    const float bi0 = __ldg(&bias[oc0]);
    const float bi1 = __ldg(&bias[oc0 + 1]);
    const size_t obase0 = ((size_t)(b * 8 + oc0) * 49 + uv) * PLANE;
    #pragma unroll
    for (int t = 0; t < 4; t++) {
        const int mrow = R0 + wid * 64 + t * 16 + (lane >> 2);
        #pragma unroll
        for (int half = 0; half < 2; half++) {
            const int m = mrow + half * 8;
            const int hp = m / PW, wp = m - hp * PW;
            if (m < NPIX && hp >= 1 && hp <= 48 && wp >= 1 && wp <= 48) {
                const size_t o = obase0 + (hp - 1) * 48 + (wp - 1);
                out[o]                  = acc[t][half * 2]     + bi0;
                out[o + (size_t)CH_STR] = acc[t][half * 2 + 1] + bi1;
            }
        }
    }
}

extern "C" void kernel_launch(void* const* d_in, const int* in_sizes, int n_in,
                              void* d_out, int out_size)
{
    const float* x    = (const float*)d_in[0];
    const float* conv = (const float*)d_in[1];
    const float* bias = (const float*)d_in[2];
    float* out        = (float*)d_out;

    cudaFuncSetAttribute(conv4d_mma,
                         cudaFuncAttributeMaxDynamicSharedMemorySize, SMEM_BYTES);

    dim3 grid(5, 49, 2);   // 490 blocks
    conv4d_mma<<<grid, NTHREADS, SMEM_BYTES>>>(x, conv, bias, out);
}

// round 13
// speedup vs baseline: 1.1381x; 1.1381x over previous
#include <cuda_runtime.h>
#include <cuda_bf16.h>
#include <cstdint>

#define PW 50
#define NPIX 2500            // 50*50 padded pixel rows per (b,u,v)
#define PLANE 2304           // 48*48
#define CH_STR 112896        // 7*7*2304
#define RPB 256              // pixel rows per block (4 warps x 64)
#define MARG 64              // sA margin (covers tap shifts +-51)
#define SA_ROWS 384          // MARG + RPB + MARG
#define LO_OFF 6144          // lo plane byte offset (384*16)
#define NTHREADS 128

__device__ __forceinline__ uint32_t cvt2(float lo, float hi) {   // {lo16,hi16} bf16x2
    uint32_t r;
    asm("cvt.rn.bf16x2.f32 %0, %1, %2;" : "=r"(r) : "f"(hi), "f"(lo));
    return r;
}
__device__ __forceinline__ void ldm4(uint32_t& r0, uint32_t& r1, uint32_t& r2,
                                     uint32_t& r3, uint32_t a) {
    asm volatile("ldmatrix.sync.aligned.m8n8.x4.shared.b16 {%0,%1,%2,%3}, [%4];"
                 : "=r"(r0), "=r"(r1), "=r"(r2), "=r"(r3) : "r"(a));
}
__device__ __forceinline__ void mma16816(float* c, uint32_t a0, uint32_t a1,
                                         uint32_t a2, uint32_t a3,
                                         uint32_t b0, uint32_t b1) {
    asm volatile(
        "mma.sync.aligned.m16n8k16.row.col.f32.bf16.bf16.f32 "
        "{%0,%1,%2,%3}, {%4,%5,%6,%7}, {%8,%9}, {%0,%1,%2,%3};"
        : "+f"(c[0]), "+f"(c[1]), "+f"(c[2]), "+f"(c[3])
        : "r"(a0), "r"(a1), "r"(a2), "r"(a3), "r"(b0), "r"(b1));
}
__device__ __forceinline__ void mma1688(float* c, uint32_t a0, uint32_t a1,
                                        uint32_t b0) {
    asm volatile(
        "mma.sync.aligned.m16n8k8.row.col.f32.bf16.bf16.f32 "
        "{%0,%1,%2,%3}, {%4,%5}, {%6}, {%0,%1,%2,%3};"
        : "+f"(c[0]), "+f"(c[1]), "+f"(c[2]), "+f"(c[3])
        : "r"(a0), "r"(a1), "r"(b0));
}
__device__ __forceinline__ void sts128(uint32_t a, uint32_t r0, uint32_t r1,
                                       uint32_t r2, uint32_t r3) {
    asm volatile("st.shared.v4.b32 [%0], {%1,%2,%3,%4};"
                 :: "r"(a), "r"(r0), "r"(r1), "r"(r2), "r"(r3) : "memory");
}

// x: [2][8][7][7][48][48] f32, conv: [8][648], bias: [8], out: [2][8][7][7][48][48] f32
__global__ __launch_bounds__(NTHREADS, 6) void conv4d_mma(
    const float* __restrict__ x,
    const float* __restrict__ conv,
    const float* __restrict__ bias,
    float* __restrict__ out)
{
    // sA: hi plane rows [0,384) at +0, lo plane at +LO_OFF; 16B/row (8 bf16 ch)
    __shared__ __align__(16) uint32_t sA4[2 * SA_ROWS * 4];   // 12288 B
    __shared__ uint2 sBF[81 * 32];                            // 20736 B

    const int tid  = threadIdx.x;
    const int wid  = tid >> 5;
    const int lane = tid & 31;
    const int R0   = blockIdx.x * RPB;
    const int uv   = blockIdx.y;
    const int u    = uv / 7, v = uv % 7;
    const int b    = blockIdx.z;

    const uint32_t sA = (uint32_t)__cvta_generic_to_shared(sA4);

    // ---- B fragments: sBF[tap*32+ln] = {Whi pair, Wlo pair} ----
    for (int e = tid; e < 81 * 32; e += NTHREADS) {
        const int tap = e >> 5, ln = e & 31;
        const int o = ln >> 2, c0 = (ln & 3) * 2;
        const float w0 = conv[o * 648 + tap * 8 + c0];
        const float w1 = conv[o * 648 + tap * 8 + c0 + 1];
        const uint32_t hi01 = cvt2(w0, w1);
        const float hf0 = __uint_as_float(hi01 << 16);
        const float hf1 = __uint_as_float(hi01 & 0xFFFF0000u);
        sBF[e] = make_uint2(hi01, cvt2(w0 - hf0, w1 - hf1));
    }
    // ---- zero sA (margins/padding rows stay 0) ----
    {
        const uint4 z = make_uint4(0, 0, 0, 0);
        uint4* p = (uint4*)sA4;
        #pragma unroll
        for (int j = tid; j < 2 * SA_ROWS; j += NTHREADS) p[j] = z;
    }

    // ---- valid (i0,i1) phases ----
    int ph_poff[9], ph_tap[9], nph = 0;
    #pragma unroll
    for (int i0 = 0; i0 < 3; i0++) {
        const int uu = u + i0 - 1;
        if (uu < 0 || uu >= 7) continue;
        #pragma unroll
        for (int i1 = 0; i1 < 3; i1++) {
            const int vv = v + i1 - 1;
            if (vv < 0 || vv >= 7) continue;
            ph_poff[nph] = (uu * 7 + vv) * PLANE;
            ph_tap[nph]  = (i0 * 3 + i1) * 9;
            nph++;
        }
    }
    const float* xb = x + (size_t)b * 8 * CH_STR;

    // ---- per-thread transpose rows: 3 rows each (384 / 128) ----
    int rw_src[3]; uint32_t rw_sa[3]; bool rw_ok[3];
    #pragma unroll
    for (int k = 0; k < 3; k++) {
        const int j = tid + k * NTHREADS;       // 0..383
        const int m = R0 - MARG + j;
        const int mc = m < 0 ? 0 : m;
        const int hp = mc / PW, wp = mc - hp * PW;
        rw_ok[k]  = (m >= 0) && (m < NPIX) &&
                    (hp >= 1) && (hp <= 48) && (wp >= 1) && (wp <= 48);
        rw_src[k] = (hp - 1) * 48 + (wp - 1);
        rw_sa[k]  = sA + j * 16;
    }

    // ---- per-warp ldmatrix base addresses (4 M-tiles of 16 rows) ----
    const int lnrow = lane & 15;
    const uint32_t plane_off = (lane < 16) ? 0u : (uint32_t)LO_OFF;
    uint32_t abase[4];
    #pragma unroll
    for (int t = 0; t < 4; t++)
        abase[t] = sA + plane_off + (MARG + wid * 64 + t * 16 + lnrow) * 16;

    float acc[4][4];
    #pragma unroll
    for (int t = 0; t < 4; t++)
        #pragma unroll
        for (int i = 0; i < 4; i++) acc[t][i] = 0.0f;

    for (int p = 0; p < nph; p++) {
        __syncthreads();   // previous phase's ldmatrix done before overwrite
        const float* src0 = xb + ph_poff[p];
        #pragma unroll
        for (int k = 0; k < 3; k++) {
            if (!rw_ok[k]) continue;
            const float* s = src0 + rw_src[k];
            float vch[8];
            #pragma unroll
            for (int c = 0; c < 8; c++) vch[c] = __ldg(s + c * CH_STR);
            uint32_t hi[4], lo[4];
            #pragma unroll
            for (int q = 0; q < 4; q++) {
                hi[q] = cvt2(vch[2 * q], vch[2 * q + 1]);
                const float hf0 = __uint_as_float(hi[q] << 16);
                const float hf1 = __uint_as_float(hi[q] & 0xFFFF0000u);
                lo[q] = cvt2(vch[2 * q] - hf0, vch[2 * q + 1] - hf1);
            }
            sts128(rw_sa[k], hi[0], hi[1], hi[2], hi[3]);
            sts128(rw_sa[k] + LO_OFF, lo[0], lo[1], lo[2], lo[3]);
        }
        __syncthreads();

        const int tapbase = ph_tap[p];
        #pragma unroll
        for (int t9 = 0; t9 < 9; t9++) {
            const int s16 = ((t9 / 3 - 1) * PW + (t9 % 3 - 1)) * 16;   // byte shift
            const uint2 bf = sBF[(tapbase + t9) * 32 + lane];
            #pragma unroll
            for (int t = 0; t < 4; t++) {
                uint32_t r0, r1, r2, r3;
                ldm4(r0, r1, r2, r3, abase[t] + s16);
                // (a0,a1)=xhi rows, (a2,a3)=xlo rows
                mma16816(acc[t], r0, r1, r0, r1, bf.x, bf.y);   // xhi*(Whi+Wlo)
                mma1688 (acc[t], r2, r3, bf.x);                 // xlo*Whi
            }
        }
    }

    // ---- epilogue ----
    const int oc0 = (lane & 3) * 2;
    const float bi0 = __ldg(&bias[oc0]);
    const float bi1 = __ldg(&bias[oc0 + 1]);
    const size_t obase0 = ((size_t)(b * 8 + oc0) * 49 + uv) * PLANE;
    #pragma unroll
    for (int t = 0; t < 4; t++) {
        const int mrow = R0 + wid * 64 + t * 16 + (lane >> 2);
        #pragma unroll
        for (int half = 0; half < 2; half++) {
            const int m = mrow + half * 8;
            const int hp = m / PW, wp = m - hp * PW;
            if (m < NPIX && hp >= 1 && hp <= 48 && wp >= 1 && wp <= 48) {
                const size_t o = obase0 + (hp - 1) * 48 + (wp - 1);
                out[o]                  = acc[t][half * 2]     + bi0;
                out[o + (size_t)CH_STR] = acc[t][half * 2 + 1] + bi1;
            }
        }
    }
}

extern "C" void kernel_launch(void* const* d_in, const int* in_sizes, int n_in,
                              void* d_out, int out_size)
{
    const float* x    = (const float*)d_in[0];
    const float* conv = (const float*)d_in[1];
    const float* bias = (const float*)d_in[2];
    float* out        = (float*)d_out;

    dim3 grid(10, 49, 2);   // 980 blocks; 10 x 256 rows cover 2500 padded pixels
    conv4d_mma<<<grid, NTHREADS>>>(x, conv, bias, out);
}